// round 15
// baseline (speedup 1.0000x reference)
#include <cuda_runtime.h>
#include <cuda_bf16.h>
#include <cstdint>

// Problem constants (fixed shapes for this bench)
#define B_NODES 16384
#define K_NEIGH 15
#define D_FEAT  256          // 64 float4 per row
#define D_VEC4  (D_FEAT / 4) // 64
#define CHUNK   5            // neighbors prefetched per batch (10 float4 in flight)

// Single-wave persistent grid: 4 blocks/SM * 148 SMs, 8 warps/block.
#define GRID_BLOCKS 592
#define TOTAL_WARPS (GRID_BLOCKS * 8)   // 4736 row-workers

// --- Main gather-mean kernel -----------------------------------------------
// Persistent: one wave of 592 blocks (4/SM at 60 regs); each warp loops over
// output rows with stride TOTAL_WARPS (3-4 rows each), keeping the LDG stream
// continuously in flight instead of draining at 3.5 wave boundaries.
//
// Per row: lane l accumulates float4 columns l and l+32; K=15 processed in
// chunks of 5 with all 10 float4 loads issued before any adds. The kernel
// runs at the full-chip LTS read cap (~6300 B/cyc, 252 MB gather), so
// everything else is overhead minimization.
//
// Index dtype detected in-kernel: for int64 little-endian data, raw words
// 1,3,5 are high halves of indices < 19997 => all zero; for int32 they are
// random indices (all-zero probability ~1e-13). One broadcast cache line.
__global__ __launch_bounds__(256)
void mean_agg_kernel(const int* __restrict__ idx_raw,
                     const float4* __restrict__ feats,
                     float4* __restrict__ out) {
    const int warp0 = (blockIdx.x * blockDim.x + threadIdx.x) >> 5;
    const int lane  = threadIdx.x & 31;

    // In-warp dtype detection (uniform broadcast loads, one cache line).
    const bool is64 = (__ldg(&idx_raw[1]) | __ldg(&idx_raw[3]) | __ldg(&idx_raw[5])) == 0;

    for (int row = warp0; row < B_NODES; row += TOTAL_WARPS) {
        const int base = row * K_NEIGH;

        // Load all neighbor ids up front (warp-uniform broadcast).
        int ids[K_NEIGH];
        #pragma unroll
        for (int k = 0; k < K_NEIGH; k++) {
            ids[k] = is64 ? __ldg(&idx_raw[(base + k) * 2])  // low word of int64
                          : __ldg(&idx_raw[base + k]);
        }

        float4 a0 = make_float4(0.f, 0.f, 0.f, 0.f);
        float4 a1 = make_float4(0.f, 0.f, 0.f, 0.f);

        #pragma unroll
        for (int c = 0; c < K_NEIGH; c += CHUNK) {
            float4 v0[CHUNK], v1[CHUNK];
            // Batch all loads of this chunk first -> deep MLP.
            #pragma unroll
            for (int j = 0; j < CHUNK; j++) {
                const float4* frow = feats + (size_t)ids[c + j] * D_VEC4;
                v0[j] = __ldg(frow + lane);
                v1[j] = __ldg(frow + lane + 32);
            }
            #pragma unroll
            for (int j = 0; j < CHUNK; j++) {
                a0.x += v0[j].x; a0.y += v0[j].y; a0.z += v0[j].z; a0.w += v0[j].w;
                a1.x += v1[j].x; a1.y += v1[j].y; a1.z += v1[j].z; a1.w += v1[j].w;
            }
        }

        const float s = 1.0f / (float)K_NEIGH;
        a0.x *= s; a0.y *= s; a0.z *= s; a0.w *= s;
        a1.x *= s; a1.y *= s; a1.z *= s; a1.w *= s;

        // Streaming stores: out is written once, never re-read; preserve L2
        // capacity for the feature table.
        float4* orow = out + (size_t)row * D_VEC4;
        __stcs(orow + lane,      a0);
        __stcs(orow + lane + 32, a1);
    }
}

extern "C" void kernel_launch(void* const* d_in, const int* in_sizes, int n_in,
                              void* d_out, int out_size) {
    const int*    idx_raw = (const int*)d_in[0];     // int64 or int32, detected in-kernel
    const float4* feats   = (const float4*)d_in[1];  // [U, 256] fp32
    float4*       out     = (float4*)d_out;          // [B, 256] fp32

    mean_agg_kernel<<<GRID_BLOCKS, 256>>>(idx_raw, feats, out);
}